// round 8
// baseline (speedup 1.0000x reference)
#include <cuda_runtime.h>

#define NN 50000
#define EE 800000
#define GG 500
#define LL 3
#define NB1 ((NN + 1023) / 1024)

typedef unsigned long long u64;

__device__ __forceinline__ u64 ffma2(u64 a, u64 b, u64 c) {
    u64 d; asm("fma.rn.f32x2 %0,%1,%2,%3;" : "=l"(d) : "l"(a), "l"(b), "l"(c)); return d;
}
__device__ __forceinline__ u64 dup2(float v) {
    u64 r; asm("mov.b64 %0,{%1,%1};" : "=l"(r) : "f"(v)); return r;
}
__device__ __forceinline__ float2 upk2(u64 v) {
    float2 f; asm("mov.b64 {%0,%1},%2;" : "=f"(f.x), "=f"(f.y) : "l"(v)); return f;
}

// ---------------- scratch (static device globals; no allocation) ----------------
__device__ int   g_is64;
__device__ int   g_degi[NN];
__device__ float g_degf[NN];
__device__ float g_dinv[NN];
__device__ int   g_ptr[NN + 1];
__device__ int   g_cnt[NN];
__device__ int   g_bsum[64];
__device__ int   g_boff[65];
__device__ int   g_csrc[EE];
__device__ float g_cw[EE];
__device__ float g_xc[NN * 128];   // [x | s] concat, row stride 128
__device__ float g_y[NN * 64];     // xc @ W1 (pre-aggregation GIN features)
__device__ float g_z[NN * 64];     // relu(agg(y)+b1) -> input of GIN gemm2
__device__ float g_hs[NN * 64];    // s @ gcnW
__device__ float g_x2[NN * 64];

// ---------------- index loading: int64 vs int32 auto-detect ----------------
__device__ __forceinline__ int ld_idx(const void* p, long i) {
    if (g_is64) return (int)((const long long*)p)[i];
    return ((const int*)p)[i];
}

__global__ void detect_k(const int* w) {
    if (blockIdx.x == 0 && threadIdx.x == 0) {
        int nz = 0;
#pragma unroll
        for (int j = 0; j < 8; j++)
            if (w[2 * j + 1] != 0) nz++;
        g_is64 = (nz == 0) ? 1 : 0;   // int64 little-endian => odd words are 0
    }
}

// ---------------- degree histogram ----------------
__global__ void hist_k(const void* ei) {
    int e = blockIdx.x * blockDim.x + threadIdx.x;
    if (e < EE) {
        int d = ld_idx(ei, (long)EE + e);
        atomicAdd(&g_degi[d], 1);
    }
}

__global__ void deg_k() {
    int i = blockIdx.x * blockDim.x + threadIdx.x;
    if (i < NN) {
        float d = (float)(g_degi[i] + 1);   // +1 self loop
        g_degf[i] = d;
        g_dinv[i] = rsqrtf(d);
    }
}

// ---------------- multi-block exclusive scan over degrees ----------------
__global__ void scan1_k() {
    __shared__ int sh[1024];
    int tid = threadIdx.x;
    int i = blockIdx.x * 1024 + tid;
    int v = (i < NN) ? g_degi[i] : 0;
    sh[tid] = v;
    __syncthreads();
    for (int off = 1; off < 1024; off <<= 1) {
        int t = (tid >= off) ? sh[tid - off] : 0;
        __syncthreads();
        sh[tid] += t;
        __syncthreads();
    }
    int incl = sh[tid];
    if (i < NN) g_ptr[i] = incl - v;
    if (tid == 1023) g_bsum[blockIdx.x] = incl;
}

__global__ void scan2_k() {
    if (threadIdx.x == 0) {
        int c = 0;
        for (int b = 0; b < NB1; b++) { g_boff[b] = c; c += g_bsum[b]; }
        g_boff[NB1] = c;
    }
}

__global__ void scan3_k() {
    int i = blockIdx.x * blockDim.x + threadIdx.x;
    if (i < NN) g_ptr[i] += g_boff[i >> 10];
    if (i == 0) g_ptr[NN] = g_boff[NB1];
}

// ---------------- CSR fill (src ids + gcn edge weights, grouped by dst) ----------------
__global__ void fill_k(const void* ei) {
    int e = blockIdx.x * blockDim.x + threadIdx.x;
    if (e < EE) {
        int sn = ld_idx(ei, e);
        int dn = ld_idx(ei, (long)EE + e);
        int pos = g_ptr[dn] + atomicAdd(&g_cnt[dn], 1);
        g_csrc[pos] = sn;
        g_cw[pos] = g_dinv[sn] * g_dinv[dn];
    }
}

// ---------------- fused GIN(y) + GCN(hs) aggregation ----------------
// warp per dst node; lanes 0-15 handle y (plain sum), lanes 16-31 handle hs
// (enorm-weighted sum). One coalesced 2x256B gather per edge covers both.
__global__ void agg_fused_k(const float* __restrict__ b1, const float* __restrict__ bg) {
    int nd = (blockIdx.x * blockDim.x + threadIdx.x) >> 5;
    if (nd >= NN) return;
    int lane = threadIdx.x & 31;
    int l4 = lane & 15;
    bool isY = lane < 16;
    const float4* base = isY ? (const float4*)g_y : (const float4*)g_hs;
    int b = g_ptr[nd], e = g_ptr[nd + 1];
    float4 a0 = make_float4(0.f, 0.f, 0.f, 0.f);
    float4 a1 = make_float4(0.f, 0.f, 0.f, 0.f);
    int i = b;
    for (; i + 1 < e; i += 2) {
        int s0 = g_csrc[i], s1 = g_csrc[i + 1];
        float w0 = isY ? 1.f : g_cw[i];
        float w1 = isY ? 1.f : g_cw[i + 1];
        float4 v0 = base[(long)s0 * 16 + l4];
        float4 v1 = base[(long)s1 * 16 + l4];
        a0.x = fmaf(w0, v0.x, a0.x); a0.y = fmaf(w0, v0.y, a0.y);
        a0.z = fmaf(w0, v0.z, a0.z); a0.w = fmaf(w0, v0.w, a0.w);
        a1.x = fmaf(w1, v1.x, a1.x); a1.y = fmaf(w1, v1.y, a1.y);
        a1.z = fmaf(w1, v1.z, a1.z); a1.w = fmaf(w1, v1.w, a1.w);
    }
    if (i < e) {
        int s0 = g_csrc[i];
        float w0 = isY ? 1.f : g_cw[i];
        float4 v0 = base[(long)s0 * 16 + l4];
        a0.x = fmaf(w0, v0.x, a0.x); a0.y = fmaf(w0, v0.y, a0.y);
        a0.z = fmaf(w0, v0.z, a0.z); a0.w = fmaf(w0, v0.w, a0.w);
    }
    a0.x += a1.x; a0.y += a1.y; a0.z += a1.z; a0.w += a1.w;
    // self term: weight 1 for GIN, 1/deg for GCN
    float ws = isY ? 1.f : (1.f / g_degf[nd]);
    float4 vs = base[(long)nd * 16 + l4];
    a0.x = fmaf(ws, vs.x, a0.x); a0.y = fmaf(ws, vs.y, a0.y);
    a0.z = fmaf(ws, vs.z, a0.z); a0.w = fmaf(ws, vs.w, a0.w);
    if (isY) {
        float4 r;
        r.x = fmaxf(a0.x + b1[4 * l4 + 0], 0.f);
        r.y = fmaxf(a0.y + b1[4 * l4 + 1], 0.f);
        r.z = fmaxf(a0.z + b1[4 * l4 + 2], 0.f);
        r.w = fmaxf(a0.w + b1[4 * l4 + 3], 0.f);
        ((float4*)g_z)[(long)nd * 16 + l4] = r;
    } else {
        float4 r;
        r.x = tanhf(a0.x + bg[4 * l4 + 0]);
        r.y = tanhf(a0.y + bg[4 * l4 + 1]);
        r.z = tanhf(a0.z + bg[4 * l4 + 2]);
        r.w = tanhf(a0.w + bg[4 * l4 + 3]);
        ((float4*)g_xc)[(long)nd * 32 + 16 + l4] = r;
    }
}

// ---------------- GEMM: out[n x 64] = act(in[n x K] @ W[K x 64] + b) ----------------
// FFMA2 (fma.rn.f32x2) path with ROW-PAIR packed accumulators:
//  - input tile stored k-major (sInT[k][row]) so each thread's 8 rows are a
//    contiguous 32B run -> a-pairs load as conflict-free LDS.64
//  - weights keep the proven conflict-free stride-68 LDS.128, duplicated {w,w}
//  - acc2[j2][c] u64 = rows {8rt+2j2, 8rt+2j2+1} for col 4ct+c -> 32 regs
// Inner loop per k: 16 FFMA2 + 4 mov + 5 LDS  (fma-pipe-bound at 2x scalar)
template <int K, int ACT>
__global__ void __launch_bounds__(256) gemm64_k(
        const float* __restrict__ in, int ldin,
        const float* __restrict__ Wm, const float* __restrict__ bias, int n,
        float* __restrict__ outA, int ldA) {
    constexpr int KC = (K < 32) ? K : 32;
    __shared__ __align__(16) float sInT[KC][130];  // k-major; stride even -> 8B-aligned pairs
    __shared__ __align__(16) float sW[KC][68];     // 68*4B = 272 = 16*17 -> aligned LDS.128

    int tid = threadIdx.x;
    int ct = tid & 15;    // cols 4*ct .. 4*ct+3
    int rt = tid >> 4;    // rows 8*rt .. 8*rt+7
    int rowBase = blockIdx.x * 128;

    u64 acc2[4][4];       // [row-pair][col]
#pragma unroll
    for (int j2 = 0; j2 < 4; j2++)
#pragma unroll
        for (int c = 0; c < 4; c++) acc2[j2][c] = 0ull;

    for (int kb = 0; kb < K; kb += KC) {
        // fill sInT transposed: thread handles (row r, k-quad q)
        for (int idx = tid; idx < 128 * (KC / 4); idx += 256) {
            int r = idx / (KC / 4), q = idx - r * (KC / 4);
            int gr = rowBase + r;
            float4 v = (gr < n) ? *(const float4*)&in[(long)gr * ldin + kb + 4 * q]
                                : make_float4(0.f, 0.f, 0.f, 0.f);
            sInT[4 * q + 0][r] = v.x;
            sInT[4 * q + 1][r] = v.y;
            sInT[4 * q + 2][r] = v.z;
            sInT[4 * q + 3][r] = v.w;
        }
        for (int idx = tid; idx < KC * 64; idx += 256) {
            int k = idx >> 6, c = idx & 63;
            sW[k][c] = Wm[(long)(kb + k) * 64 + c];
        }
        __syncthreads();
#pragma unroll 8
        for (int k = 0; k < KC; k++) {
            float4 w = *(const float4*)&sW[k][4 * ct];
            u64 wd0 = dup2(w.x), wd1 = dup2(w.y), wd2 = dup2(w.z), wd3 = dup2(w.w);
            u64 a2[4];
#pragma unroll
            for (int j2 = 0; j2 < 4; j2++)
                a2[j2] = *(const u64*)&sInT[k][8 * rt + 2 * j2];
#pragma unroll
            for (int j2 = 0; j2 < 4; j2++) {
                acc2[j2][0] = ffma2(a2[j2], wd0, acc2[j2][0]);
                acc2[j2][1] = ffma2(a2[j2], wd1, acc2[j2][1]);
                acc2[j2][2] = ffma2(a2[j2], wd2, acc2[j2][2]);
                acc2[j2][3] = ffma2(a2[j2], wd3, acc2[j2][3]);
            }
        }
        __syncthreads();
    }

    float bs[4];
#pragma unroll
    for (int c = 0; c < 4; c++) bs[c] = bias ? bias[4 * ct + c] : 0.f;
#pragma unroll
    for (int j2 = 0; j2 < 4; j2++) {
        int gr0 = rowBase + 8 * rt + 2 * j2;
#pragma unroll
        for (int c = 0; c < 4; c++) {
            float2 p = upk2(acc2[j2][c]);
            float v0 = p.x + bs[c];
            float v1 = p.y + bs[c];
            if (ACT) { v0 = fmaxf(v0, 0.f); v1 = fmaxf(v1, 0.f); }
            if (gr0 < n)     outA[(long)gr0 * ldA + 4 * ct + c] = v0;
            if (gr0 + 1 < n) outA[(long)(gr0 + 1) * ldA + 4 * ct + c] = v1;
        }
    }
}

// ---------------- fused global add pool + post + readout + log_softmax ----------------
__global__ void poolhead_k(const void* __restrict__ batch,
                           const float* __restrict__ postW, const float* __restrict__ postb,
                           const float* __restrict__ roW, const float* __restrict__ rob,
                           float* __restrict__ out) {
    int g = blockIdx.x;
    int t = threadIdx.x;   // 64 threads, one column each
    int lo = 0, hi = NN;
    while (lo < hi) { int mid = (lo + hi) >> 1; if (ld_idx(batch, mid) < g) lo = mid + 1; else hi = mid; }
    int beg = lo;
    hi = NN;
    while (lo < hi) { int mid = (lo + hi) >> 1; if (ld_idx(batch, mid) < g + 1) lo = mid + 1; else hi = mid; }
    int end = lo;

    float acc = 0.f;
    for (int nd = beg; nd < end; nd++) acc += g_x2[(long)nd * 64 + t];

    __shared__ float sg[64], sh1[64], sl[10];
    sg[t] = acc;
    __syncthreads();
    float a = postb[t];
#pragma unroll
    for (int k = 0; k < 64; k++) a = fmaf(sg[k], postW[k * 64 + t], a);
    sh1[t] = fmaxf(a, 0.f);
    __syncthreads();
    if (t < 10) {
        float r = rob[t];
#pragma unroll
        for (int k = 0; k < 64; k++) r = fmaf(sh1[k], roW[k * 10 + t], r);
        sl[t] = r;
    }
    __syncthreads();
    if (t == 0) {
        float m = sl[0];
#pragma unroll
        for (int c = 1; c < 10; c++) m = fmaxf(m, sl[c]);
        float sum = 0.f;
#pragma unroll
        for (int c = 0; c < 10; c++) sum += expf(sl[c] - m);
        float lse = m + logf(sum);
#pragma unroll
        for (int c = 0; c < 10; c++) out[g * 10 + c] = sl[c] - lse;
    }
}

// ---------------- launch ----------------
extern "C" void kernel_launch(void* const* d_in, const int* in_sizes, int n_in,
                              void* d_out, int out_size) {
    const float* x_in  = (const float*)d_in[0];
    const float* s_in  = (const float*)d_in[1];
    const void*  ei    = d_in[2];
    const void*  batch = d_in[3];
    const float* preW  = (const float*)d_in[4];
    const float* preb  = (const float*)d_in[5];
    const float* embW  = (const float*)d_in[6];
    const float* embb  = (const float*)d_in[7];
    const float* ginW1 = (const float*)d_in[8];
    const float* ginb1 = (const float*)d_in[9];
    const float* ginW2 = (const float*)d_in[10];
    const float* ginb2 = (const float*)d_in[11];
    const float* gcnW  = (const float*)d_in[12];
    const float* gcnb  = (const float*)d_in[13];
    const float* whpW  = (const float*)d_in[14];
    const float* whpb  = (const float*)d_in[15];
    const float* postW = (const float*)d_in[16];
    const float* postb = (const float*)d_in[17];
    const float* roW   = (const float*)d_in[18];
    const float* rob   = (const float*)d_in[19];
    float* out = (float*)d_out;

    void *p_degi, *p_cnt, *p_xc, *p_y, *p_z, *p_hs, *p_x2;
    cudaGetSymbolAddress(&p_degi, g_degi);
    cudaGetSymbolAddress(&p_cnt, g_cnt);
    cudaGetSymbolAddress(&p_xc, g_xc);
    cudaGetSymbolAddress(&p_y, g_y);
    cudaGetSymbolAddress(&p_z, g_z);
    cudaGetSymbolAddress(&p_hs, g_hs);
    cudaGetSymbolAddress(&p_x2, g_x2);
    float* xc = (float*)p_xc;
    float* ybuf = (float*)p_y;
    float* zbuf = (float*)p_z;
    float* hs = (float*)p_hs;
    float* x2 = (float*)p_x2;

    cudaMemsetAsync(p_degi, 0, NN * sizeof(int), 0);
    cudaMemsetAsync(p_cnt, 0, NN * sizeof(int), 0);

    detect_k<<<1, 32>>>((const int*)ei);

    const int TB = 256;
    const int gridE = (EE + TB - 1) / TB;
    const int gridN = (NN + TB - 1) / TB;
    const int gridW = (NN * 32 + TB - 1) / TB;
    const int gridM = (NN + 127) / 128;

    hist_k<<<gridE, TB>>>(ei);
    deg_k<<<gridN, TB>>>();
    scan1_k<<<NB1, 1024>>>();
    scan2_k<<<1, 32>>>();
    scan3_k<<<gridN, TB>>>();
    fill_k<<<gridE, TB>>>(ei);

    // pre: x -> xc[:, :64];  emb: s -> xc[:, 64:]
    gemm64_k<128, 0><<<gridM, TB>>>(x_in, 128, preW, preb, NN, xc, 128);
    gemm64_k<16, 0><<<gridM, TB>>>(s_in, 16, embW, embb, NN, xc + 64, 128);

    for (int i = 0; i < LL; i++) {
        // y = xc @ W1 (bias deferred to agg); hs = s @ gcnW (s = xc[:,64:])
        gemm64_k<128, 0><<<gridM, TB>>>(xc, 128, ginW1 + (long)i * 128 * 64, nullptr,
                                        NN, ybuf, 64);
        gemm64_k<64, 0><<<gridM, TB>>>(xc + 64, 128, gcnW + (long)i * 64 * 64, nullptr,
                                       NN, hs, 64);
        // z = relu(y_self + sum y_src + b1); s' = tanh(sum w*hs + hs_self/deg + bg)
        agg_fused_k<<<gridW, TB>>>(ginb1 + i * 64, gcnb + i * 64);
        // x = relu(z @ W2 + b2) -> xc[:, :64]
        gemm64_k<64, 1><<<gridM, TB>>>(zbuf, 64, ginW2 + (long)i * 64 * 64, ginb2 + i * 64,
                                       NN, xc, 128);
    }

    gemm64_k<128, 0><<<gridM, TB>>>(xc, 128, whpW, whpb, NN, x2, 64);
    poolhead_k<<<GG, 64>>>(batch, postW, postb, roW, rob, out);
}

// round 9
// speedup vs baseline: 1.0833x; 1.0833x over previous
#include <cuda_runtime.h>
#include <cuda_fp16.h>

#define NN 50000
#define EE 800000
#define GG 500
#define LL 3
#define NB1 ((NN + 1023) / 1024)

// ---------------- scratch (static device globals; no allocation) ----------------
__device__ int    g_is64;
__device__ int    g_degi[NN];
__device__ float  g_degf[NN];
__device__ float  g_dinv[NN];
__device__ int    g_ptr[NN + 1];
__device__ int    g_cnt[NN];
__device__ int    g_bsum[64];
__device__ int    g_boff[65];
__device__ int    g_csrc[EE];
__device__ float  g_cw[EE];
__device__ float  g_xc[NN * 128];   // [x | s] concat, row stride 128 (fp32)
__device__ __half g_y16[NN * 64];   // xc @ W1 in fp16 (gather buffer)
__device__ __half g_hs16[NN * 64];  // s @ gcnW in fp16 (gather buffer)
__device__ float  g_z[NN * 64];     // relu(agg(y)+b1) -> input of GIN gemm2
__device__ float  g_x2[NN * 64];

// ---------------- index loading: int64 vs int32 auto-detect ----------------
__device__ __forceinline__ int ld_idx(const void* p, long i) {
    if (g_is64) return (int)((const long long*)p)[i];
    return ((const int*)p)[i];
}

__global__ void detect_k(const int* w) {
    if (blockIdx.x == 0 && threadIdx.x == 0) {
        int nz = 0;
#pragma unroll
        for (int j = 0; j < 8; j++)
            if (w[2 * j + 1] != 0) nz++;
        g_is64 = (nz == 0) ? 1 : 0;   // int64 little-endian => odd words are 0
    }
}

// ---------------- degree histogram ----------------
__global__ void hist_k(const void* ei) {
    int e = blockIdx.x * blockDim.x + threadIdx.x;
    if (e < EE) {
        int d = ld_idx(ei, (long)EE + e);
        atomicAdd(&g_degi[d], 1);
    }
}

// ---------------- multi-block exclusive scan over degrees (+ deg/dinv fused) ----------------
__global__ void scan1_k() {
    __shared__ int sh[1024];
    int tid = threadIdx.x;
    int i = blockIdx.x * 1024 + tid;
    int v = (i < NN) ? g_degi[i] : 0;
    if (i < NN) {
        float d = (float)(v + 1);   // +1 self loop
        g_degf[i] = d;
        g_dinv[i] = rsqrtf(d);
    }
    sh[tid] = v;
    __syncthreads();
    for (int off = 1; off < 1024; off <<= 1) {
        int t = (tid >= off) ? sh[tid - off] : 0;
        __syncthreads();
        sh[tid] += t;
        __syncthreads();
    }
    int incl = sh[tid];
    if (i < NN) g_ptr[i] = incl - v;
    if (tid == 1023) g_bsum[blockIdx.x] = incl;
}

__global__ void scan2_k() {
    if (threadIdx.x == 0) {
        int c = 0;
        for (int b = 0; b < NB1; b++) { g_boff[b] = c; c += g_bsum[b]; }
        g_boff[NB1] = c;
    }
}

__global__ void scan3_k() {
    int i = blockIdx.x * blockDim.x + threadIdx.x;
    if (i < NN) g_ptr[i] += g_boff[i >> 10];
    if (i == 0) g_ptr[NN] = g_boff[NB1];
}

// ---------------- CSR fill (src ids + gcn edge weights, grouped by dst) ----------------
__global__ void fill_k(const void* ei) {
    int e = blockIdx.x * blockDim.x + threadIdx.x;
    if (e < EE) {
        int sn = ld_idx(ei, e);
        int dn = ld_idx(ei, (long)EE + e);
        int pos = g_ptr[dn] + atomicAdd(&g_cnt[dn], 1);
        g_csrc[pos] = sn;
        g_cw[pos] = g_dinv[sn] * g_dinv[dn];
    }
}

// ---------------- fused GIN(y) + GCN(hs) aggregation, fp16 gathers ----------------
// warp per dst node; lanes 0-15 handle y (plain sum), lanes 16-31 handle hs
// (enorm-weighted sum). Each lane loads 4 halves (8B); warp covers both 128B
// rows per edge fully coalesced. Accumulation in fp32.
__global__ void agg_fused_k(const float* __restrict__ b1, const float* __restrict__ bg) {
    int nd = (blockIdx.x * blockDim.x + threadIdx.x) >> 5;
    if (nd >= NN) return;
    int lane = threadIdx.x & 31;
    int l4 = lane & 15;
    bool isY = lane < 16;
    const uint2* base = isY ? (const uint2*)g_y16 : (const uint2*)g_hs16;  // row = 16 uint2
    int b = g_ptr[nd], e = g_ptr[nd + 1];
    float4 a0 = make_float4(0.f, 0.f, 0.f, 0.f);
    float4 a1 = make_float4(0.f, 0.f, 0.f, 0.f);
    int i = b;
    for (; i + 1 < e; i += 2) {
        int s0 = g_csrc[i], s1 = g_csrc[i + 1];
        float w0 = isY ? 1.f : g_cw[i];
        float w1 = isY ? 1.f : g_cw[i + 1];
        uint2 u0 = base[(long)s0 * 16 + l4];
        uint2 u1 = base[(long)s1 * 16 + l4];
        float2 p0 = __half22float2(*(const __half2*)&u0.x);
        float2 p1 = __half22float2(*(const __half2*)&u0.y);
        float2 q0 = __half22float2(*(const __half2*)&u1.x);
        float2 q1 = __half22float2(*(const __half2*)&u1.y);
        a0.x = fmaf(w0, p0.x, a0.x); a0.y = fmaf(w0, p0.y, a0.y);
        a0.z = fmaf(w0, p1.x, a0.z); a0.w = fmaf(w0, p1.y, a0.w);
        a1.x = fmaf(w1, q0.x, a1.x); a1.y = fmaf(w1, q0.y, a1.y);
        a1.z = fmaf(w1, q1.x, a1.z); a1.w = fmaf(w1, q1.y, a1.w);
    }
    if (i < e) {
        int s0 = g_csrc[i];
        float w0 = isY ? 1.f : g_cw[i];
        uint2 u0 = base[(long)s0 * 16 + l4];
        float2 p0 = __half22float2(*(const __half2*)&u0.x);
        float2 p1 = __half22float2(*(const __half2*)&u0.y);
        a0.x = fmaf(w0, p0.x, a0.x); a0.y = fmaf(w0, p0.y, a0.y);
        a0.z = fmaf(w0, p1.x, a0.z); a0.w = fmaf(w0, p1.y, a0.w);
    }
    a0.x += a1.x; a0.y += a1.y; a0.z += a1.z; a0.w += a1.w;
    // self term: weight 1 for GIN, 1/deg for GCN
    float ws = isY ? 1.f : (1.f / g_degf[nd]);
    {
        uint2 us = base[(long)nd * 16 + l4];
        float2 p0 = __half22float2(*(const __half2*)&us.x);
        float2 p1 = __half22float2(*(const __half2*)&us.y);
        a0.x = fmaf(ws, p0.x, a0.x); a0.y = fmaf(ws, p0.y, a0.y);
        a0.z = fmaf(ws, p1.x, a0.z); a0.w = fmaf(ws, p1.y, a0.w);
    }
    if (isY) {
        float4 r;
        r.x = fmaxf(a0.x + b1[4 * l4 + 0], 0.f);
        r.y = fmaxf(a0.y + b1[4 * l4 + 1], 0.f);
        r.z = fmaxf(a0.z + b1[4 * l4 + 2], 0.f);
        r.w = fmaxf(a0.w + b1[4 * l4 + 3], 0.f);
        ((float4*)g_z)[(long)nd * 16 + l4] = r;
    } else {
        float4 r;
        r.x = tanhf(a0.x + bg[4 * l4 + 0]);
        r.y = tanhf(a0.y + bg[4 * l4 + 1]);
        r.z = tanhf(a0.z + bg[4 * l4 + 2]);
        r.w = tanhf(a0.w + bg[4 * l4 + 3]);
        ((float4*)g_xc)[(long)nd * 32 + 16 + l4] = r;
    }
}

// ---------------- GEMM: out[n x 64] = act(in[n x K] @ W[K x 64] + b) ----------------
// Scalar-FFMA path (proven): block = 128 rows x 64 cols, 256 threads,
// 8x4 register tile, KC<=32 k-chunks, conflict-free float4 weight reads.
// HOUT=1 writes fp16 (4 halves packed into one aligned 8B store).
template <int K, int ACT, int HOUT>
__global__ void __launch_bounds__(256) gemm64_k(
        const float* __restrict__ in, int ldin,
        const float* __restrict__ Wm, const float* __restrict__ bias, int n,
        void* __restrict__ outP, int ldA) {
    constexpr int KC = (K < 32) ? K : 32;
    __shared__ float sIn[128][KC + 1];
    __shared__ float sW[KC][68];   // row stride 68 floats => 16B-aligned float4 reads

    int tid = threadIdx.x;
    int ct = tid & 15;    // col tile: cols 4*ct .. 4*ct+3
    int rt = tid >> 4;    // row tile: rows 8*rt .. 8*rt+7
    int rowBase = blockIdx.x * 128;

    float acc[8][4];
    float bseed[4];
#pragma unroll
    for (int c = 0; c < 4; c++) bseed[c] = bias ? bias[4 * ct + c] : 0.f;
#pragma unroll
    for (int r = 0; r < 8; r++)
#pragma unroll
        for (int c = 0; c < 4; c++) acc[r][c] = bseed[c];

    for (int kb = 0; kb < K; kb += KC) {
        for (int idx = tid; idx < 128 * KC; idx += 256) {
            int r = idx / KC, k = idx - r * KC;
            int gr = rowBase + r;
            sIn[r][k] = (gr < n) ? in[(long)gr * ldin + kb + k] : 0.f;
        }
        for (int idx = tid; idx < KC * 64; idx += 256) {
            int k = idx >> 6, c = idx & 63;
            sW[k][c] = Wm[(long)(kb + k) * 64 + c];
        }
        __syncthreads();
#pragma unroll 8
        for (int k = 0; k < KC; k++) {
            float4 w = *(const float4*)&sW[k][4 * ct];
            float a[8];
#pragma unroll
            for (int j = 0; j < 8; j++) a[j] = sIn[8 * rt + j][k];
#pragma unroll
            for (int j = 0; j < 8; j++) {
                acc[j][0] = fmaf(a[j], w.x, acc[j][0]);
                acc[j][1] = fmaf(a[j], w.y, acc[j][1]);
                acc[j][2] = fmaf(a[j], w.z, acc[j][2]);
                acc[j][3] = fmaf(a[j], w.w, acc[j][3]);
            }
        }
        __syncthreads();
    }

#pragma unroll
    for (int r = 0; r < 8; r++) {
        int gr = rowBase + 8 * rt + r;
        if (gr < n) {
            float v0 = acc[r][0], v1 = acc[r][1], v2 = acc[r][2], v3 = acc[r][3];
            if (ACT) {
                v0 = fmaxf(v0, 0.f); v1 = fmaxf(v1, 0.f);
                v2 = fmaxf(v2, 0.f); v3 = fmaxf(v3, 0.f);
            }
            if (HOUT) {
                __half* o = (__half*)outP;
                __half2 h01 = __floats2half2_rn(v0, v1);
                __half2 h23 = __floats2half2_rn(v2, v3);
                uint2 pk;
                pk.x = *(const unsigned*)&h01;
                pk.y = *(const unsigned*)&h23;
                *(uint2*)&o[(long)gr * ldA + 4 * ct] = pk;
            } else {
                float* o = (float*)outP;
                o[(long)gr * ldA + 4 * ct + 0] = v0;
                o[(long)gr * ldA + 4 * ct + 1] = v1;
                o[(long)gr * ldA + 4 * ct + 2] = v2;
                o[(long)gr * ldA + 4 * ct + 3] = v3;
            }
        }
    }
}

// ---------------- fused global add pool + post + readout + log_softmax ----------------
__global__ void poolhead_k(const void* __restrict__ batch,
                           const float* __restrict__ postW, const float* __restrict__ postb,
                           const float* __restrict__ roW, const float* __restrict__ rob,
                           float* __restrict__ out) {
    int g = blockIdx.x;
    int t = threadIdx.x;   // 64 threads, one column each
    int lo = 0, hi = NN;
    while (lo < hi) { int mid = (lo + hi) >> 1; if (ld_idx(batch, mid) < g) lo = mid + 1; else hi = mid; }
    int beg = lo;
    hi = NN;
    while (lo < hi) { int mid = (lo + hi) >> 1; if (ld_idx(batch, mid) < g + 1) lo = mid + 1; else hi = mid; }
    int end = lo;

    float acc = 0.f;
    for (int nd = beg; nd < end; nd++) acc += g_x2[(long)nd * 64 + t];

    __shared__ float sg[64], sh1[64], sl[10];
    sg[t] = acc;
    __syncthreads();
    float a = postb[t];
#pragma unroll
    for (int k = 0; k < 64; k++) a = fmaf(sg[k], postW[k * 64 + t], a);
    sh1[t] = fmaxf(a, 0.f);
    __syncthreads();
    if (t < 10) {
        float r = rob[t];
#pragma unroll
        for (int k = 0; k < 64; k++) r = fmaf(sh1[k], roW[k * 10 + t], r);
        sl[t] = r;
    }
    __syncthreads();
    if (t == 0) {
        float m = sl[0];
#pragma unroll
        for (int c = 1; c < 10; c++) m = fmaxf(m, sl[c]);
        float sum = 0.f;
#pragma unroll
        for (int c = 0; c < 10; c++) sum += expf(sl[c] - m);
        float lse = m + logf(sum);
#pragma unroll
        for (int c = 0; c < 10; c++) out[g * 10 + c] = sl[c] - lse;
    }
}

// ---------------- launch ----------------
extern "C" void kernel_launch(void* const* d_in, const int* in_sizes, int n_in,
                              void* d_out, int out_size) {
    const float* x_in  = (const float*)d_in[0];
    const float* s_in  = (const float*)d_in[1];
    const void*  ei    = d_in[2];
    const void*  batch = d_in[3];
    const float* preW  = (const float*)d_in[4];
    const float* preb  = (const float*)d_in[5];
    const float* embW  = (const float*)d_in[6];
    const float* embb  = (const float*)d_in[7];
    const float* ginW1 = (const float*)d_in[8];
    const float* ginb1 = (const float*)d_in[9];
    const float* ginW2 = (const float*)d_in[10];
    const float* ginb2 = (const float*)d_in[11];
    const float* gcnW  = (const float*)d_in[12];
    const float* gcnb  = (const float*)d_in[13];
    const float* whpW  = (const float*)d_in[14];
    const float* whpb  = (const float*)d_in[15];
    const float* postW = (const float*)d_in[16];
    const float* postb = (const float*)d_in[17];
    const float* roW   = (const float*)d_in[18];
    const float* rob   = (const float*)d_in[19];
    float* out = (float*)d_out;

    void *p_degi, *p_cnt, *p_xc, *p_y16, *p_hs16, *p_z, *p_x2;
    cudaGetSymbolAddress(&p_degi, g_degi);
    cudaGetSymbolAddress(&p_cnt, g_cnt);
    cudaGetSymbolAddress(&p_xc, g_xc);
    cudaGetSymbolAddress(&p_y16, g_y16);
    cudaGetSymbolAddress(&p_hs16, g_hs16);
    cudaGetSymbolAddress(&p_z, g_z);
    cudaGetSymbolAddress(&p_x2, g_x2);
    float* xc = (float*)p_xc;
    float* zbuf = (float*)p_z;
    float* x2 = (float*)p_x2;

    cudaMemsetAsync(p_degi, 0, NN * sizeof(int), 0);
    cudaMemsetAsync(p_cnt, 0, NN * sizeof(int), 0);

    detect_k<<<1, 32>>>((const int*)ei);

    const int TB = 256;
    const int gridE = (EE + TB - 1) / TB;
    const int gridN = (NN + TB - 1) / TB;
    const int gridW = (NN * 32 + TB - 1) / TB;
    const int gridM = (NN + 127) / 128;

    hist_k<<<gridE, TB>>>(ei);
    scan1_k<<<NB1, 1024>>>();
    scan2_k<<<1, 32>>>();
    scan3_k<<<gridN, TB>>>();
    fill_k<<<gridE, TB>>>(ei);

    // pre: x -> xc[:, :64];  emb: s -> xc[:, 64:]
    gemm64_k<128, 0, 0><<<gridM, TB>>>(x_in, 128, preW, preb, NN, xc, 128);
    gemm64_k<16, 0, 0><<<gridM, TB>>>(s_in, 16, embW, embb, NN, xc + 64, 128);

    for (int i = 0; i < LL; i++) {
        // y = xc @ W1 (fp16 out, bias deferred to agg); hs = s @ gcnW (fp16 out)
        gemm64_k<128, 0, 1><<<gridM, TB>>>(xc, 128, ginW1 + (long)i * 128 * 64, nullptr,
                                           NN, p_y16, 64);
        gemm64_k<64, 0, 1><<<gridM, TB>>>(xc + 64, 128, gcnW + (long)i * 64 * 64, nullptr,
                                          NN, p_hs16, 64);
        // z = relu(y_self + sum y_src + b1); s' = tanh(sum w*hs + hs_self/deg + bg)
        agg_fused_k<<<gridW, TB>>>(ginb1 + i * 64, gcnb + i * 64);
        // x = relu(z @ W2 + b2) -> xc[:, :64]
        gemm64_k<64, 1, 0><<<gridM, TB>>>(zbuf, 64, ginW2 + (long)i * 64 * 64, ginb2 + i * 64,
                                          NN, xc, 128);
    }

    gemm64_k<128, 0, 0><<<gridM, TB>>>(xc, 128, whpW, whpb, NN, x2, 64);
    poolhead_k<<<GG, 64>>>(batch, postW, postb, roW, rob, out);
}

// round 13
// speedup vs baseline: 1.5962x; 1.4735x over previous
#include <cuda_runtime.h>
#include <cuda_fp16.h>
#include <cstdint>

#define NN 50000
#define EE 800000
#define GG 500
#define LL 3
#define NB1 ((NN + 1023) / 1024)

// ---------------- mma.sync helpers (baseline PTX, no sm_103a features) ----------------
__device__ __forceinline__ uint32_t smem_u32(const void* p) {
    uint32_t a;
    asm("{ .reg .u64 t; cvta.to.shared.u64 t, %1; cvt.u32.u64 %0, t; }" : "=r"(a) : "l"(p));
    return a;
}
__device__ __forceinline__ void ldsm4(uint32_t& r0, uint32_t& r1, uint32_t& r2, uint32_t& r3,
                                      uint32_t addr) {
    asm volatile("ldmatrix.sync.aligned.m8n8.x4.shared.b16 {%0,%1,%2,%3}, [%4];"
                 : "=r"(r0), "=r"(r1), "=r"(r2), "=r"(r3) : "r"(addr));
}
__device__ __forceinline__ void mma16816(float* c, uint32_t a0, uint32_t a1, uint32_t a2,
                                         uint32_t a3, uint32_t b0, uint32_t b1) {
    asm volatile("mma.sync.aligned.m16n8k16.row.col.f32.f16.f16.f32 "
                 "{%0,%1,%2,%3}, {%4,%5,%6,%7}, {%8,%9}, {%0,%1,%2,%3};"
                 : "+f"(c[0]), "+f"(c[1]), "+f"(c[2]), "+f"(c[3])
                 : "r"(a0), "r"(a1), "r"(a2), "r"(a3), "r"(b0), "r"(b1));
}

// ---------------- scratch (static device globals; no allocation) ----------------
__device__ int    g_is64;
__device__ int    g_degi[NN];
__device__ float  g_degf[NN];
__device__ float  g_dinv[NN];
__device__ int    g_ptr[NN + 1];
__device__ int    g_cnt[NN];
__device__ int    g_bsum[64];
__device__ int    g_boff[65];
__device__ int    g_csrc[EE];
__device__ float  g_cw[EE];
__device__ __half g_x16[NN * 128];   // x input fp16
__device__ __half g_s16i[NN * 16];   // s input fp16
__device__ __half g_xc[NN * 128];    // [x | s] concat fp16, row stride 128
__device__ __half g_y16[NN * 64];    // xc @ W1 fp16
__device__ __half g_hs16[NN * 64];   // s @ gcnW fp16
__device__ __half g_z16[NN * 64];    // relu(agg(y)+b1) fp16
__device__ float  g_x2[NN * 64];
__device__ __half g_w16[66560];      // all weights fp16, transposed [n][k]

// weight buffer offsets (halves)
#define W_GIN1 0        // 3 x 64x128
#define W_GCN  24576    // 3 x 64x64
#define W_GIN2 36864    // 3 x 64x64
#define W_WHP  49152    // 64x128
#define W_PRE  57344    // 64x128
#define W_EMB  65536    // 64x16

// ---------------- index loading: int64 vs int32 auto-detect ----------------
__device__ __forceinline__ int ld_idx(const void* p, long i) {
    if (g_is64) return (int)((const long long*)p)[i];
    return ((const int*)p)[i];
}

__global__ void detect_k(const int* w) {
    if (blockIdx.x == 0 && threadIdx.x == 0) {
        int nz = 0;
#pragma unroll
        for (int j = 0; j < 8; j++)
            if (w[2 * j + 1] != 0) nz++;
        g_is64 = (nz == 0) ? 1 : 0;
    }
}

// ---------------- weight convert + transpose to fp16, [n][k] layout ----------------
__global__ void convw_k(const float* __restrict__ gin1, const float* __restrict__ gcn,
                        const float* __restrict__ gin2, const float* __restrict__ whp,
                        const float* __restrict__ pre, const float* __restrict__ emb) {
    int idx = blockIdx.x * blockDim.x + threadIdx.x;
    if (idx >= 66560) return;
    float v;
    if (idx < 24576) {            // ginW1 [l][k=128][n=64] -> [l][n][k]
        int l = idx / 8192, r = idx % 8192, n = r / 128, k = r % 128;
        v = gin1[l * 8192 + k * 64 + n];
    } else if (idx < 36864) {     // gcnW
        int r0 = idx - 24576; int l = r0 / 4096, r = r0 % 4096, n = r / 64, k = r % 64;
        v = gcn[l * 4096 + k * 64 + n];
    } else if (idx < 49152) {     // ginW2
        int r0 = idx - 36864; int l = r0 / 4096, r = r0 % 4096, n = r / 64, k = r % 64;
        v = gin2[l * 4096 + k * 64 + n];
    } else if (idx < 57344) {     // whp [128][64]
        int r = idx - 49152; int n = r / 128, k = r % 128;
        v = whp[k * 64 + n];
    } else if (idx < 65536) {     // pre [128][64]
        int r = idx - 57344; int n = r / 128, k = r % 128;
        v = pre[k * 64 + n];
    } else {                      // emb [16][64]
        int r = idx - 65536; int n = r / 16, k = r % 16;
        v = emb[k * 64 + n];
    }
    g_w16[idx] = __float2half_rn(v);
}

// ---------------- fp32 -> fp16 input conversion ----------------
__global__ void convin_k(const float* __restrict__ src, __half* __restrict__ dst, int cnt4) {
    int i = blockIdx.x * blockDim.x + threadIdx.x;
    if (i < cnt4) {
        float4 v = ((const float4*)src)[i];
        __half2 a = __floats2half2_rn(v.x, v.y);
        __half2 b = __floats2half2_rn(v.z, v.w);
        uint2 pk;
        pk.x = *(const unsigned*)&a;
        pk.y = *(const unsigned*)&b;
        ((uint2*)dst)[i] = pk;
    }
}

// ---------------- degree histogram ----------------
__global__ void hist_k(const void* ei) {
    int e = blockIdx.x * blockDim.x + threadIdx.x;
    if (e < EE) {
        int d = ld_idx(ei, (long)EE + e);
        atomicAdd(&g_degi[d], 1);
    }
}

// ---------------- scan phase 1 (+ deg/dinv fused) ----------------
__global__ void scan1_k() {
    __shared__ int sh[1024];
    int tid = threadIdx.x;
    int i = blockIdx.x * 1024 + tid;
    int v = (i < NN) ? g_degi[i] : 0;
    if (i < NN) {
        float d = (float)(v + 1);
        g_degf[i] = d;
        g_dinv[i] = rsqrtf(d);
    }
    sh[tid] = v;
    __syncthreads();
    for (int off = 1; off < 1024; off <<= 1) {
        int t = (tid >= off) ? sh[tid - off] : 0;
        __syncthreads();
        sh[tid] += t;
        __syncthreads();
    }
    int incl = sh[tid];
    if (i < NN) g_ptr[i] = incl - v;
    if (tid == 1023) g_bsum[blockIdx.x] = incl;
}

__global__ void scan2_k() {
    __shared__ int sh[64];
    int t = threadIdx.x;
    int v = (t < NB1) ? g_bsum[t] : 0;
    sh[t] = v;
    __syncthreads();
    for (int off = 1; off < 64; off <<= 1) {
        int x = (t >= off) ? sh[t - off] : 0;
        __syncthreads();
        sh[t] += x;
        __syncthreads();
    }
    if (t <= NB1) g_boff[t] = sh[t] - v;
}

__global__ void scan3_k() {
    int i = blockIdx.x * blockDim.x + threadIdx.x;
    if (i < NN) g_ptr[i] += g_boff[i >> 10];
    if (i == 0) g_ptr[NN] = g_boff[NB1];
}

// ---------------- CSR fill ----------------
__global__ void fill_k(const void* ei) {
    int e = blockIdx.x * blockDim.x + threadIdx.x;
    if (e < EE) {
        int sn = ld_idx(ei, e);
        int dn = ld_idx(ei, (long)EE + e);
        int pos = g_ptr[dn] + atomicAdd(&g_cnt[dn], 1);
        g_csrc[pos] = sn;
        g_cw[pos] = g_dinv[sn] * g_dinv[dn];
    }
}

// ---------------- fused GIN(y) + GCN(hs) aggregation, fp16 gathers ----------------
__global__ void agg_fused_k(const float* __restrict__ b1, const float* __restrict__ bg) {
    int nd = (blockIdx.x * blockDim.x + threadIdx.x) >> 5;
    if (nd >= NN) return;
    int lane = threadIdx.x & 31;
    int l4 = lane & 15;
    bool isY = lane < 16;
    const uint2* base = isY ? (const uint2*)g_y16 : (const uint2*)g_hs16;
    int b = g_ptr[nd], e = g_ptr[nd + 1];
    float4 a0 = make_float4(0.f, 0.f, 0.f, 0.f);
    float4 a1 = make_float4(0.f, 0.f, 0.f, 0.f);
    int i = b;
    for (; i + 1 < e; i += 2) {
        int s0 = g_csrc[i], s1 = g_csrc[i + 1];
        float w0 = isY ? 1.f : g_cw[i];
        float w1 = isY ? 1.f : g_cw[i + 1];
        uint2 u0 = base[(long)s0 * 16 + l4];
        uint2 u1 = base[(long)s1 * 16 + l4];
        float2 p0 = __half22float2(*(const __half2*)&u0.x);
        float2 p1 = __half22float2(*(const __half2*)&u0.y);
        float2 q0 = __half22float2(*(const __half2*)&u1.x);
        float2 q1 = __half22float2(*(const __half2*)&u1.y);
        a0.x = fmaf(w0, p0.x, a0.x); a0.y = fmaf(w0, p0.y, a0.y);
        a0.z = fmaf(w0, p1.x, a0.z); a0.w = fmaf(w0, p1.y, a0.w);
        a1.x = fmaf(w1, q0.x, a1.x); a1.y = fmaf(w1, q0.y, a1.y);
        a1.z = fmaf(w1, q1.x, a1.z); a1.w = fmaf(w1, q1.y, a1.w);
    }
    if (i < e) {
        int s0 = g_csrc[i];
        float w0 = isY ? 1.f : g_cw[i];
        uint2 u0 = base[(long)s0 * 16 + l4];
        float2 p0 = __half22float2(*(const __half2*)&u0.x);
        float2 p1 = __half22float2(*(const __half2*)&u0.y);
        a0.x = fmaf(w0, p0.x, a0.x); a0.y = fmaf(w0, p0.y, a0.y);
        a0.z = fmaf(w0, p1.x, a0.z); a0.w = fmaf(w0, p1.y, a0.w);
    }
    a0.x += a1.x; a0.y += a1.y; a0.z += a1.z; a0.w += a1.w;
    float ws = isY ? 1.f : (1.f / g_degf[nd]);
    {
        uint2 us = base[(long)nd * 16 + l4];
        float2 p0 = __half22float2(*(const __half2*)&us.x);
        float2 p1 = __half22float2(*(const __half2*)&us.y);
        a0.x = fmaf(ws, p0.x, a0.x); a0.y = fmaf(ws, p0.y, a0.y);
        a0.z = fmaf(ws, p1.x, a0.z); a0.w = fmaf(ws, p1.y, a0.w);
    }
    if (isY) {
        float r0 = fmaxf(a0.x + b1[4 * l4 + 0], 0.f);
        float r1 = fmaxf(a0.y + b1[4 * l4 + 1], 0.f);
        float r2 = fmaxf(a0.z + b1[4 * l4 + 2], 0.f);
        float r3 = fmaxf(a0.w + b1[4 * l4 + 3], 0.f);
        __half2 h01 = __floats2half2_rn(r0, r1);
        __half2 h23 = __floats2half2_rn(r2, r3);
        uint2 pk; pk.x = *(const unsigned*)&h01; pk.y = *(const unsigned*)&h23;
        ((uint2*)g_z16)[(long)nd * 16 + l4] = pk;
    } else {
        float r0 = tanhf(a0.x + bg[4 * l4 + 0]);
        float r1 = tanhf(a0.y + bg[4 * l4 + 1]);
        float r2 = tanhf(a0.z + bg[4 * l4 + 2]);
        float r3 = tanhf(a0.w + bg[4 * l4 + 3]);
        __half2 h01 = __floats2half2_rn(r0, r1);
        __half2 h23 = __floats2half2_rn(r2, r3);
        uint2 pk; pk.x = *(const unsigned*)&h01; pk.y = *(const unsigned*)&h23;
        ((uint2*)g_xc)[(long)nd * 32 + 16 + l4] = pk;
    }
}

// ---------------- HMMA GEMM: out[128-tile x 64] = act(A @ Wt^T + b) ----------------
// A: in[row][k] fp16 (ldin halves). Wt: [64][K] fp16 (row.col B layout).
// mma.sync.m16n8k16 f32 accum. 256 threads = 8 warps; warp = 16 rows x 64 cols.
template <int K, int ACT, int HOUT>
__global__ void __launch_bounds__(256) hgemm_k(
        const __half* __restrict__ in, int ldin,
        const __half* __restrict__ wt, const float* __restrict__ bias, int n,
        void* __restrict__ outP, int ldA) {
    constexpr int KP = K + 8;             // padded row (halves) -> conflict-free ldmatrix
    constexpr int KQ = K / 4;
    extern __shared__ __half dsm[];
    __half* sA = dsm;                     // [128][KP]
    __half* sB = dsm + 128 * KP;          // [64][KP]

    int tid = threadIdx.x;
    int w = tid >> 5, lane = tid & 31;
    int rowBase = blockIdx.x * 128;

    // fill A (zero-pad OOB rows)
    for (int idx = tid; idx < 128 * KQ; idx += 256) {
        int r = idx / KQ, q = idx - r * KQ;
        int gr = rowBase + r;
        uint2 v = make_uint2(0u, 0u);
        if (gr < n) v = *(const uint2*)&in[(long)gr * ldin + 4 * q];
        *(uint2*)&sA[r * KP + 4 * q] = v;
    }
    // fill B
    for (int idx = tid; idx < 64 * KQ; idx += 256) {
        int r = idx / KQ, q = idx - r * KQ;
        *(uint2*)&sB[r * KP + 4 * q] = *(const uint2*)&wt[(long)r * K + 4 * q];
    }
    __syncthreads();

    float acc[8][4];
#pragma unroll
    for (int t = 0; t < 8; t++)
#pragma unroll
        for (int j = 0; j < 4; j++) acc[t][j] = 0.f;

    // ldmatrix source addresses
    uint32_t aAddr = smem_u32(&sA[(16 * w + (lane & 15)) * KP + ((lane >> 4) << 3)]);
    int bRow = (lane & 7) + ((lane >> 4) << 3);
    int bCol = ((lane >> 3) & 1) << 3;
    uint32_t bAddr0 = smem_u32(&sB[bRow * KP + bCol]);

#pragma unroll
    for (int kk = 0; kk < K / 16; kk++) {
        uint32_t a0, a1, a2, a3;
        ldsm4(a0, a1, a2, a3, aAddr + kk * 32);
#pragma unroll
        for (int ntp = 0; ntp < 4; ntp++) {
            uint32_t b0, b1, b2, b3;
            ldsm4(b0, b1, b2, b3, bAddr0 + (ntp * 16 * KP + kk * 16) * 2);
            mma16816(acc[2 * ntp],     a0, a1, a2, a3, b0, b1);
            mma16816(acc[2 * ntp + 1], a0, a1, a2, a3, b2, b3);
        }
    }

    // epilogue: thread t of warp -> rows {16w + t/4, +8}, cols nt*8 + (t%4)*2
    int r0 = rowBase + 16 * w + (lane >> 2);
    int cb = (lane & 3) * 2;
#pragma unroll
    for (int nt = 0; nt < 8; nt++) {
        int c = nt * 8 + cb;
        float v00 = acc[nt][0], v01 = acc[nt][1], v10 = acc[nt][2], v11 = acc[nt][3];
        if (bias) {
            float bc0 = bias[c], bc1 = bias[c + 1];
            v00 += bc0; v01 += bc1; v10 += bc0; v11 += bc1;
        }
        if (ACT) {
            v00 = fmaxf(v00, 0.f); v01 = fmaxf(v01, 0.f);
            v10 = fmaxf(v10, 0.f); v11 = fmaxf(v11, 0.f);
        }
        if (HOUT) {
            __half* o = (__half*)outP;
            if (r0 < n) {
                __half2 h = __floats2half2_rn(v00, v01);
                *(__half2*)&o[(long)r0 * ldA + c] = h;
            }
            if (r0 + 8 < n) {
                __half2 h = __floats2half2_rn(v10, v11);
                *(__half2*)&o[(long)(r0 + 8) * ldA + c] = h;
            }
        } else {
            float* o = (float*)outP;
            if (r0 < n)     *(float2*)&o[(long)r0 * ldA + c] = make_float2(v00, v01);
            if (r0 + 8 < n) *(float2*)&o[(long)(r0 + 8) * ldA + c] = make_float2(v10, v11);
        }
    }
}

// ---------------- fused global add pool + post + readout + log_softmax ----------------
__global__ void poolhead_k(const void* __restrict__ batch,
                           const float* __restrict__ postW, const float* __restrict__ postb,
                           const float* __restrict__ roW, const float* __restrict__ rob,
                           float* __restrict__ out) {
    int g = blockIdx.x;
    int t = threadIdx.x;
    int lo = 0, hi = NN;
    while (lo < hi) { int mid = (lo + hi) >> 1; if (ld_idx(batch, mid) < g) lo = mid + 1; else hi = mid; }
    int beg = lo;
    hi = NN;
    while (lo < hi) { int mid = (lo + hi) >> 1; if (ld_idx(batch, mid) < g + 1) lo = mid + 1; else hi = mid; }
    int end = lo;

    float acc = 0.f;
    for (int nd = beg; nd < end; nd++) acc += g_x2[(long)nd * 64 + t];

    __shared__ float sg[64], sh1[64], sl[10];
    sg[t] = acc;
    __syncthreads();
    float a = postb[t];
#pragma unroll
    for (int k = 0; k < 64; k++) a = fmaf(sg[k], postW[k * 64 + t], a);
    sh1[t] = fmaxf(a, 0.f);
    __syncthreads();
    if (t < 10) {
        float r = rob[t];
#pragma unroll
        for (int k = 0; k < 64; k++) r = fmaf(sh1[k], roW[k * 10 + t], r);
        sl[t] = r;
    }
    __syncthreads();
    if (t == 0) {
        float m = sl[0];
#pragma unroll
        for (int c = 1; c < 10; c++) m = fmaxf(m, sl[c]);
        float sum = 0.f;
#pragma unroll
        for (int c = 0; c < 10; c++) sum += expf(sl[c] - m);
        float lse = m + logf(sum);
#pragma unroll
        for (int c = 0; c < 10; c++) out[g * 10 + c] = sl[c] - lse;
    }
}

// ---------------- launch ----------------
extern "C" void kernel_launch(void* const* d_in, const int* in_sizes, int n_in,
                              void* d_out, int out_size) {
    const float* x_in  = (const float*)d_in[0];
    const float* s_in  = (const float*)d_in[1];
    const void*  ei    = d_in[2];
    const void*  batch = d_in[3];
    const float* preW  = (const float*)d_in[4];
    const float* preb  = (const float*)d_in[5];
    const float* embW  = (const float*)d_in[6];
    const float* embb  = (const float*)d_in[7];
    const float* ginW1 = (const float*)d_in[8];
    const float* ginb1 = (const float*)d_in[9];
    const float* ginW2 = (const float*)d_in[10];
    const float* ginb2 = (const float*)d_in[11];
    const float* gcnW  = (const float*)d_in[12];
    const float* gcnb  = (const float*)d_in[13];
    const float* whpW  = (const float*)d_in[14];
    const float* whpb  = (const float*)d_in[15];
    const float* postW = (const float*)d_in[16];
    const float* postb = (const float*)d_in[17];
    const float* roW   = (const float*)d_in[18];
    const float* rob   = (const float*)d_in[19];
    float* out = (float*)d_out;

    void *p_degi, *p_cnt, *p_x16, *p_s16, *p_xc, *p_y16, *p_hs16, *p_z16, *p_x2, *p_w16;
    cudaGetSymbolAddress(&p_degi, g_degi);
    cudaGetSymbolAddress(&p_cnt, g_cnt);
    cudaGetSymbolAddress(&p_x16, g_x16);
    cudaGetSymbolAddress(&p_s16, g_s16i);
    cudaGetSymbolAddress(&p_xc, g_xc);
    cudaGetSymbolAddress(&p_y16, g_y16);
    cudaGetSymbolAddress(&p_hs16, g_hs16);
    cudaGetSymbolAddress(&p_z16, g_z16);
    cudaGetSymbolAddress(&p_x2, g_x2);
    cudaGetSymbolAddress(&p_w16, g_w16);
    __half* x16 = (__half*)p_x16;
    __half* s16 = (__half*)p_s16;
    __half* xc16 = (__half*)p_xc;
    __half* w16 = (__half*)p_w16;

    // dynamic smem sizes: 192*(K+8)*2 bytes
    const int SM128 = 192 * 136 * 2;  // 52224
    const int SM64  = 192 * 72 * 2;   // 27648
    const int SM16  = 192 * 24 * 2;   // 9216
    cudaFuncSetAttribute(hgemm_k<128, 0, 1>, cudaFuncAttributeMaxDynamicSharedMemorySize, SM128);
    cudaFuncSetAttribute(hgemm_k<128, 0, 0>, cudaFuncAttributeMaxDynamicSharedMemorySize, SM128);
    cudaFuncSetAttribute(hgemm_k<64, 0, 1>,  cudaFuncAttributeMaxDynamicSharedMemorySize, SM64);
    cudaFuncSetAttribute(hgemm_k<64, 1, 1>,  cudaFuncAttributeMaxDynamicSharedMemorySize, SM64);
    cudaFuncSetAttribute(hgemm_k<16, 0, 1>,  cudaFuncAttributeMaxDynamicSharedMemorySize, SM16);

    cudaMemsetAsync(p_degi, 0, NN * sizeof(int), 0);
    cudaMemsetAsync(p_cnt, 0, NN * sizeof(int), 0);

    detect_k<<<1, 32>>>((const int*)ei);

    const int TB = 256;
    const int gridE = (EE + TB - 1) / TB;
    const int gridN = (NN + TB - 1) / TB;
    const int gridW = (NN * 32 + TB - 1) / TB;
    const int gridM = (NN + 127) / 128;   // 391 CTAs

    // weight + input conversion
    convw_k<<<(66560 + 255) / 256, 256>>>(ginW1, gcnW, ginW2, whpW, preW, embW);
    convin_k<<<(NN * 32 + 255) / 256, 256>>>(x_in, x16, NN * 32);
    convin_k<<<(NN * 4 + 255) / 256, 256>>>(s_in, s16, NN * 4);

    // CSR build
    hist_k<<<gridE, TB>>>(ei);
    scan1_k<<<NB1, 1024>>>();
    scan2_k<<<1, 64>>>();
    scan3_k<<<gridN, TB>>>();
    fill_k<<<gridE, TB>>>(ei);

    // pre: x -> xc[:, :64];  emb: s -> xc[:, 64:]
    hgemm_k<128, 0, 1><<<gridM, 256, SM128>>>(x16, 128, w16 + W_PRE, preb, NN, xc16, 128);
    hgemm_k<16, 0, 1><<<gridM, 256, SM16>>>(s16, 16, w16 + W_EMB, embb, NN, xc16 + 64, 128);

    for (int i = 0; i < LL; i++) {
        hgemm_k<128, 0, 1><<<gridM, 256, SM128>>>(xc16, 128, w16 + W_GIN1 + i * 8192, nullptr,
                                                  NN, p_y16, 64);
        hgemm_k<64, 0, 1><<<gridM, 256, SM64>>>(xc16 + 64, 128, w16 + W_GCN + i * 4096, nullptr,
                                                NN, p_hs16, 64);
        agg_fused_k<<<gridW, TB>>>(ginb1 + i * 64, gcnb + i * 64);
        hgemm_k<64, 1, 1><<<gridM, 256, SM64>>>((__half*)p_z16, 64, w16 + W_GIN2 + i * 4096,
                                                ginb2 + i * 64, NN, xc16, 128);
    }

    hgemm_k<128, 0, 0><<<gridM, 256, SM128>>>(xc16, 128, w16 + W_WHP, whpb, NN, p_x2, 64);
    poolhead_k<<<GG, 64>>>(batch, postW, postb, roW, rob, out);
}

// round 14
// speedup vs baseline: 1.6716x; 1.0472x over previous
#include <cuda_runtime.h>
#include <cuda_fp16.h>
#include <cstdint>

#define NN 50000
#define EE 800000
#define GG 500
#define LL 3
#define NB1 ((NN + 1023) / 1024)

// ---------------- mma.sync helpers (baseline PTX, no sm_103a features) ----------------
__device__ __forceinline__ uint32_t smem_u32(const void* p) {
    uint32_t a;
    asm("{ .reg .u64 t; cvta.to.shared.u64 t, %1; cvt.u32.u64 %0, t; }" : "=r"(a) : "l"(p));
    return a;
}
__device__ __forceinline__ void ldsm4(uint32_t& r0, uint32_t& r1, uint32_t& r2, uint32_t& r3,
                                      uint32_t addr) {
    asm volatile("ldmatrix.sync.aligned.m8n8.x4.shared.b16 {%0,%1,%2,%3}, [%4];"
                 : "=r"(r0), "=r"(r1), "=r"(r2), "=r"(r3) : "r"(addr));
}
__device__ __forceinline__ void mma16816(float* c, uint32_t a0, uint32_t a1, uint32_t a2,
                                         uint32_t a3, uint32_t b0, uint32_t b1) {
    asm volatile("mma.sync.aligned.m16n8k16.row.col.f32.f16.f16.f32 "
                 "{%0,%1,%2,%3}, {%4,%5,%6,%7}, {%8,%9}, {%0,%1,%2,%3};"
                 : "+f"(c[0]), "+f"(c[1]), "+f"(c[2]), "+f"(c[3])
                 : "r"(a0), "r"(a1), "r"(a2), "r"(a3), "r"(b0), "r"(b1));
}

// ---------------- scratch (static device globals; no allocation) ----------------
__device__ int    g_is64;
__device__ int    g_degi[NN];
__device__ float  g_degf[NN];
__device__ float  g_dinv[NN];
__device__ int    g_ptr[NN + 1];
__device__ int    g_cnt[NN];
__device__ int    g_bsum[64];
__device__ int    g_boff[65];
__device__ int    g_csrc[EE];
__device__ float  g_cw[EE];
__device__ __half g_xc[NN * 128];    // [x | s] concat fp16, row stride 128
__device__ __half g_y16[NN * 64];    // xc @ W1 fp16
__device__ __half g_hs16[NN * 64];   // s @ gcnW fp16
__device__ __half g_z16[NN * 64];    // relu(agg(y)+b1) fp16
__device__ float  g_x2[NN * 64];
__device__ __half g_w16[78848];      // all weights fp16, [n][k] layouts

// weight buffer offsets (halves)
#define W_DUAL 0        // 3 x [128n][128k]  (n<64: ginW1; n>=64: gcn on k>=64, 0 else)
#define W_GIN2 49152    // 3 x [64][64]
#define W_WHP  61440    // [64][128]
#define W_PRE  69632    // [64][128]
#define W_EMB  77824    // [64][16]
#define W_TOTAL 78848

// ---------------- index loading: int64 vs int32 auto-detect ----------------
__device__ __forceinline__ int ld_idx(const void* p, long i) {
    if (g_is64) return (int)((const long long*)p)[i];
    return ((const int*)p)[i];
}

__global__ void detect_k(const int* w) {
    if (blockIdx.x == 0 && threadIdx.x == 0) {
        int nz = 0;
#pragma unroll
        for (int j = 0; j < 8; j++)
            if (w[2 * j + 1] != 0) nz++;
        g_is64 = (nz == 0) ? 1 : 0;
    }
}

// ---------------- weight convert + transpose to fp16 ----------------
__global__ void convw_k(const float* __restrict__ gin1, const float* __restrict__ gcn,
                        const float* __restrict__ gin2, const float* __restrict__ whp,
                        const float* __restrict__ pre, const float* __restrict__ emb) {
    int idx = blockIdx.x * blockDim.x + threadIdx.x;
    if (idx >= W_TOTAL) return;
    float v;
    if (idx < 49152) {            // dual: [l][n=128][k=128]
        int l = idx / 16384, r = idx % 16384, n = r / 128, k = r % 128;
        if (n < 64) v = gin1[l * 8192 + k * 64 + n];                 // ginW1 [k][n]
        else if (k >= 64) v = gcn[l * 4096 + (k - 64) * 64 + (n - 64)];
        else v = 0.f;
    } else if (idx < 61440) {     // ginW2 [l][64][64]
        int r0 = idx - 49152; int l = r0 / 4096, r = r0 % 4096, n = r / 64, k = r % 64;
        v = gin2[l * 4096 + k * 64 + n];
    } else if (idx < 69632) {     // whp [128][64] -> [n][k]
        int r = idx - 61440; int n = r / 128, k = r % 128;
        v = whp[k * 64 + n];
    } else if (idx < 77824) {     // pre
        int r = idx - 69632; int n = r / 128, k = r % 128;
        v = pre[k * 64 + n];
    } else {                      // emb [16][64]
        int r = idx - 77824; int n = r / 16, k = r % 16;
        v = emb[k * 64 + n];
    }
    g_w16[idx] = __float2half_rn(v);
}

// ---------------- degree histogram ----------------
__global__ void hist_k(const void* ei) {
    int e = blockIdx.x * blockDim.x + threadIdx.x;
    if (e < EE) {
        int d = ld_idx(ei, (long)EE + e);
        atomicAdd(&g_degi[d], 1);
    }
}

// ---------------- scan phase 1 (+ deg/dinv fused) ----------------
__global__ void scan1_k() {
    __shared__ int sh[1024];
    int tid = threadIdx.x;
    int i = blockIdx.x * 1024 + tid;
    int v = (i < NN) ? g_degi[i] : 0;
    if (i < NN) {
        float d = (float)(v + 1);
        g_degf[i] = d;
        g_dinv[i] = rsqrtf(d);
    }
    sh[tid] = v;
    __syncthreads();
    for (int off = 1; off < 1024; off <<= 1) {
        int t = (tid >= off) ? sh[tid - off] : 0;
        __syncthreads();
        sh[tid] += t;
        __syncthreads();
    }
    int incl = sh[tid];
    if (i < NN) g_ptr[i] = incl - v;
    if (tid == 1023) g_bsum[blockIdx.x] = incl;
}

__global__ void scan2_k() {
    __shared__ int sh[64];
    int t = threadIdx.x;
    int v = (t < NB1) ? g_bsum[t] : 0;
    sh[t] = v;
    __syncthreads();
    for (int off = 1; off < 64; off <<= 1) {
        int x = (t >= off) ? sh[t - off] : 0;
        __syncthreads();
        sh[t] += x;
        __syncthreads();
    }
    if (t <= NB1) g_boff[t] = sh[t] - v;
}

__global__ void scan3_k() {
    int i = blockIdx.x * blockDim.x + threadIdx.x;
    if (i < NN) g_ptr[i] += g_boff[i >> 10];
    if (i == 0) g_ptr[NN] = g_boff[NB1];
}

// ---------------- CSR fill ----------------
__global__ void fill_k(const void* ei) {
    int e = blockIdx.x * blockDim.x + threadIdx.x;
    if (e < EE) {
        int sn = ld_idx(ei, e);
        int dn = ld_idx(ei, (long)EE + e);
        int pos = g_ptr[dn] + atomicAdd(&g_cnt[dn], 1);
        g_csrc[pos] = sn;
        g_cw[pos] = g_dinv[sn] * g_dinv[dn];
    }
}

// ---------------- fused GIN(y) + GCN(hs) aggregation, fp16 gathers ----------------
__global__ void agg_fused_k(const float* __restrict__ b1, const float* __restrict__ bg) {
    int nd = (blockIdx.x * blockDim.x + threadIdx.x) >> 5;
    if (nd >= NN) return;
    int lane = threadIdx.x & 31;
    int l4 = lane & 15;
    bool isY = lane < 16;
    const uint2* base = isY ? (const uint2*)g_y16 : (const uint2*)g_hs16;
    int b = g_ptr[nd], e = g_ptr[nd + 1];
    float4 a0 = make_float4(0.f, 0.f, 0.f, 0.f);
    float4 a1 = make_float4(0.f, 0.f, 0.f, 0.f);
    int i = b;
    for (; i + 1 < e; i += 2) {
        int s0 = g_csrc[i], s1 = g_csrc[i + 1];
        float w0 = isY ? 1.f : g_cw[i];
        float w1 = isY ? 1.f : g_cw[i + 1];
        uint2 u0 = base[(long)s0 * 16 + l4];
        uint2 u1 = base[(long)s1 * 16 + l4];
        float2 p0 = __half22float2(*(const __half2*)&u0.x);
        float2 p1 = __half22float2(*(const __half2*)&u0.y);
        float2 q0 = __half22float2(*(const __half2*)&u1.x);
        float2 q1 = __half22float2(*(const __half2*)&u1.y);
        a0.x = fmaf(w0, p0.x, a0.x); a0.y = fmaf(w0, p0.y, a0.y);
        a0.z = fmaf(w0, p1.x, a0.z); a0.w = fmaf(w0, p1.y, a0.w);
        a1.x = fmaf(w1, q0.x, a1.x); a1.y = fmaf(w1, q0.y, a1.y);
        a1.z = fmaf(w1, q1.x, a1.z); a1.w = fmaf(w1, q1.y, a1.w);
    }
    if (i < e) {
        int s0 = g_csrc[i];
        float w0 = isY ? 1.f : g_cw[i];
        uint2 u0 = base[(long)s0 * 16 + l4];
        float2 p0 = __half22float2(*(const __half2*)&u0.x);
        float2 p1 = __half22float2(*(const __half2*)&u0.y);
        a0.x = fmaf(w0, p0.x, a0.x); a0.y = fmaf(w0, p0.y, a0.y);
        a0.z = fmaf(w0, p1.x, a0.z); a0.w = fmaf(w0, p1.y, a0.w);
    }
    a0.x += a1.x; a0.y += a1.y; a0.z += a1.z; a0.w += a1.w;
    float ws = isY ? 1.f : (1.f / g_degf[nd]);
    {
        uint2 us = base[(long)nd * 16 + l4];
        float2 p0 = __half22float2(*(const __half2*)&us.x);
        float2 p1 = __half22float2(*(const __half2*)&us.y);
        a0.x = fmaf(ws, p0.x, a0.x); a0.y = fmaf(ws, p0.y, a0.y);
        a0.z = fmaf(ws, p1.x, a0.z); a0.w = fmaf(ws, p1.y, a0.w);
    }
    if (isY) {
        float r0 = fmaxf(a0.x + b1[4 * l4 + 0], 0.f);
        float r1 = fmaxf(a0.y + b1[4 * l4 + 1], 0.f);
        float r2 = fmaxf(a0.z + b1[4 * l4 + 2], 0.f);
        float r3 = fmaxf(a0.w + b1[4 * l4 + 3], 0.f);
        __half2 h01 = __floats2half2_rn(r0, r1);
        __half2 h23 = __floats2half2_rn(r2, r3);
        uint2 pk; pk.x = *(const unsigned*)&h01; pk.y = *(const unsigned*)&h23;
        ((uint2*)g_z16)[(long)nd * 16 + l4] = pk;
    } else {
        float r0 = tanhf(a0.x + bg[4 * l4 + 0]);
        float r1 = tanhf(a0.y + bg[4 * l4 + 1]);
        float r2 = tanhf(a0.z + bg[4 * l4 + 2]);
        float r3 = tanhf(a0.w + bg[4 * l4 + 3]);
        __half2 h01 = __floats2half2_rn(r0, r1);
        __half2 h23 = __floats2half2_rn(r2, r3);
        uint2 pk; pk.x = *(const unsigned*)&h01; pk.y = *(const unsigned*)&h23;
        ((uint2*)g_xc)[(long)nd * 32 + 16 + l4] = pk;
    }
}

// ---------------- HMMA GEMM: 128-row tile x NOUT cols = act(A @ Wt^T + b) ----------------
// A: in[row][k] fp16 (or fp32 when F32IN, converted during smem fill).
// Wt: [NOUT][K] fp16 (row.col B layout). mma.sync.m16n8k16 f32 accum.
// 256 threads = 8 warps; warp = 16 rows x NOUT cols.
// Dual-output: cols < 64 -> outA, cols >= 64 -> outB (col-64). bias only if NOUT==64.
template <int K, int NOUT, int ACT, int HOUT, int F32IN>
__global__ void __launch_bounds__(256) hgemm_k(
        const void* __restrict__ in, int ldin,
        const __half* __restrict__ wt, const float* __restrict__ bias, int n,
        void* __restrict__ outA, int ldA, void* __restrict__ outB, int ldB) {
    constexpr int KP = K + 8;             // padded row (halves) -> conflict-free ldmatrix
    constexpr int KQ = K / 4;
    extern __shared__ __half dsm[];
    __half* sA = dsm;                     // [128][KP]
    __half* sB = dsm + 128 * KP;          // [NOUT][KP]

    int tid = threadIdx.x;
    int w = tid >> 5, lane = tid & 31;
    int rowBase = blockIdx.x * 128;

    // fill A (zero-pad OOB rows; fp32->fp16 conversion inline when F32IN)
    for (int idx = tid; idx < 128 * KQ; idx += 256) {
        int r = idx / KQ, q = idx - r * KQ;
        int gr = rowBase + r;
        uint2 pk = make_uint2(0u, 0u);
        if (gr < n) {
            if (F32IN) {
                float4 v = *(const float4*)&((const float*)in)[(long)gr * ldin + 4 * q];
                __half2 h0 = __floats2half2_rn(v.x, v.y);
                __half2 h1 = __floats2half2_rn(v.z, v.w);
                pk.x = *(const unsigned*)&h0;
                pk.y = *(const unsigned*)&h1;
            } else {
                pk = *(const uint2*)&((const __half*)in)[(long)gr * ldin + 4 * q];
            }
        }
        *(uint2*)&sA[r * KP + 4 * q] = pk;
    }
    // fill B
    for (int idx = tid; idx < NOUT * KQ; idx += 256) {
        int r = idx / KQ, q = idx - r * KQ;
        *(uint2*)&sB[r * KP + 4 * q] = *(const uint2*)&wt[(long)r * K + 4 * q];
    }
    __syncthreads();

    constexpr int NT = NOUT / 8;
    float acc[NT][4];
#pragma unroll
    for (int t = 0; t < NT; t++)
#pragma unroll
        for (int j = 0; j < 4; j++) acc[t][j] = 0.f;

    uint32_t aAddr = smem_u32(&sA[(16 * w + (lane & 15)) * KP + ((lane >> 4) << 3)]);
    int bRow = (lane & 7) + ((lane >> 4) << 3);
    int bCol = ((lane >> 3) & 1) << 3;
    uint32_t bAddr0 = smem_u32(&sB[bRow * KP + bCol]);

#pragma unroll
    for (int kk = 0; kk < K / 16; kk++) {
        uint32_t a0, a1, a2, a3;
        ldsm4(a0, a1, a2, a3, aAddr + kk * 32);
#pragma unroll
        for (int ntp = 0; ntp < NT / 2; ntp++) {
            uint32_t b0, b1, b2, b3;
            ldsm4(b0, b1, b2, b3, bAddr0 + (ntp * 16 * KP + kk * 16) * 2);
            mma16816(acc[2 * ntp],     a0, a1, a2, a3, b0, b1);
            mma16816(acc[2 * ntp + 1], a0, a1, a2, a3, b2, b3);
        }
    }

    // epilogue: thread -> rows {16w + lane/4, +8}, cols nt*8 + (lane%4)*2
    int r0 = rowBase + 16 * w + (lane >> 2);
    int cb = (lane & 3) * 2;
#pragma unroll
    for (int nt = 0; nt < NT; nt++) {
        int c = nt * 8 + cb;
        float v00 = acc[nt][0], v01 = acc[nt][1], v10 = acc[nt][2], v11 = acc[nt][3];
        if (bias) {
            float bc0 = bias[c], bc1 = bias[c + 1];
            v00 += bc0; v01 += bc1; v10 += bc0; v11 += bc1;
        }
        if (ACT) {
            v00 = fmaxf(v00, 0.f); v01 = fmaxf(v01, 0.f);
            v10 = fmaxf(v10, 0.f); v11 = fmaxf(v11, 0.f);
        }
        void* op = outA;
        int col = c, ld = ldA;
        if (NOUT == 128 && c >= 64) { op = outB; col = c - 64; ld = ldB; }
        if (HOUT) {
            __half* o = (__half*)op;
            if (r0 < n) {
                __half2 h = __floats2half2_rn(v00, v01);
                *(__half2*)&o[(long)r0 * ld + col] = h;
            }
            if (r0 + 8 < n) {
                __half2 h = __floats2half2_rn(v10, v11);
                *(__half2*)&o[(long)(r0 + 8) * ld + col] = h;
            }
        } else {
            float* o = (float*)op;
            if (r0 < n)     *(float2*)&o[(long)r0 * ld + col] = make_float2(v00, v01);
            if (r0 + 8 < n) *(float2*)&o[(long)(r0 + 8) * ld + col] = make_float2(v10, v11);
        }
    }
}

// ---------------- fused global add pool + post + readout + log_softmax ----------------
__global__ void poolhead_k(const void* __restrict__ batch,
                           const float* __restrict__ postW, const float* __restrict__ postb,
                           const float* __restrict__ roW, const float* __restrict__ rob,
                           float* __restrict__ out) {
    int g = blockIdx.x;
    int t = threadIdx.x;
    int lo = 0, hi = NN;
    while (lo < hi) { int mid = (lo + hi) >> 1; if (ld_idx(batch, mid) < g) lo = mid + 1; else hi = mid; }
    int beg = lo;
    hi = NN;
    while (lo < hi) { int mid = (lo + hi) >> 1; if (ld_idx(batch, mid) < g + 1) lo = mid + 1; else hi = mid; }
    int end = lo;

    float acc = 0.f;
    for (int nd = beg; nd < end; nd++) acc += g_x2[(long)nd * 64 + t];

    __shared__ float sg[64], sh1[64], sl[10];
    sg[t] = acc;
    __syncthreads();
    float a = postb[t];
#pragma unroll
    for (int k = 0; k < 64; k++) a = fmaf(sg[k], postW[k * 64 + t], a);
    sh1[t] = fmaxf(a, 0.f);
    __syncthreads();
    if (t < 10) {
        float r = rob[t];
#pragma unroll
        for (int k = 0; k < 64; k++) r = fmaf(sh1[k], roW[k * 10 + t], r);
        sl[t] = r;
    }
    __syncthreads();
    if (t == 0) {
        float m = sl[0];
#pragma unroll
        for (int c = 1; c < 10; c++) m = fmaxf(m, sl[c]);
        float sum = 0.f;
#pragma unroll
        for (int c = 0; c < 10; c++) sum += expf(sl[c] - m);
        float lse = m + logf(sum);
#pragma unroll
        for (int c = 0; c < 10; c++) out[g * 10 + c] = sl[c] - lse;
    }
}

// ---------------- launch ----------------
extern "C" void kernel_launch(void* const* d_in, const int* in_sizes, int n_in,
                              void* d_out, int out_size) {
    const float* x_in  = (const float*)d_in[0];
    const float* s_in  = (const float*)d_in[1];
    const void*  ei    = d_in[2];
    const void*  batch = d_in[3];
    const float* preW  = (const float*)d_in[4];
    const float* preb  = (const float*)d_in[5];
    const float* embW  = (const float*)d_in[6];
    const float* embb  = (const float*)d_in[7];
    const float* ginW1 = (const float*)d_in[8];
    const float* ginb1 = (const float*)d_in[9];
    const float* ginW2 = (const float*)d_in[10];
    const float* ginb2 = (const float*)d_in[11];
    const float* gcnW  = (const float*)d_in[12];
    const float* gcnb  = (const float*)d_in[13];
    const float* whpW  = (const float*)d_in[14];
    const float* whpb  = (const float*)d_in[15];
    const float* postW = (const float*)d_in[16];
    const float* postb = (const float*)d_in[17];
    const float* roW   = (const float*)d_in[18];
    const float* rob   = (const float*)d_in[19];
    float* out = (float*)d_out;

    void *p_degi, *p_cnt, *p_xc, *p_y16, *p_hs16, *p_z16, *p_x2;
    cudaGetSymbolAddress(&p_degi, g_degi);
    cudaGetSymbolAddress(&p_cnt, g_cnt);
    cudaGetSymbolAddress(&p_xc, g_xc);
    cudaGetSymbolAddress(&p_y16, g_y16);
    cudaGetSymbolAddress(&p_hs16, g_hs16);
    cudaGetSymbolAddress(&p_z16, g_z16);
    cudaGetSymbolAddress(&p_x2, g_x2);
    __half* xc16 = (__half*)p_xc;
    void* p_w16;
    cudaGetSymbolAddress(&p_w16, g_w16);
    __half* w16 = (__half*)p_w16;

    // dynamic smem: (128 + NOUT) * (K + 8) * 2 bytes
    const int SM128  = 192 * 136 * 2;  // 52224  (K=128, NOUT=64)
    const int SMDUAL = 256 * 136 * 2;  // 69632  (K=128, NOUT=128)
    const int SM64   = 192 * 72 * 2;   // 27648  (K=64)
    const int SM16   = 192 * 24 * 2;   // 9216   (K=16)
    cudaFuncSetAttribute(hgemm_k<128, 64, 0, 1, 1>,  cudaFuncAttributeMaxDynamicSharedMemorySize, SM128);
    cudaFuncSetAttribute(hgemm_k<16, 64, 0, 1, 1>,   cudaFuncAttributeMaxDynamicSharedMemorySize, SM16);
    cudaFuncSetAttribute(hgemm_k<128, 128, 0, 1, 0>, cudaFuncAttributeMaxDynamicSharedMemorySize, SMDUAL);
    cudaFuncSetAttribute(hgemm_k<64, 64, 1, 1, 0>,   cudaFuncAttributeMaxDynamicSharedMemorySize, SM64);
    cudaFuncSetAttribute(hgemm_k<128, 64, 0, 0, 0>,  cudaFuncAttributeMaxDynamicSharedMemorySize, SM128);

    cudaMemsetAsync(p_degi, 0, NN * sizeof(int), 0);
    cudaMemsetAsync(p_cnt, 0, NN * sizeof(int), 0);

    detect_k<<<1, 32>>>((const int*)ei);

    const int TB = 256;
    const int gridE = (EE + TB - 1) / TB;
    const int gridN = (NN + TB - 1) / TB;
    const int gridW = (NN * 32 + TB - 1) / TB;
    const int gridM = (NN + 127) / 128;   // 391 CTAs

    convw_k<<<(W_TOTAL + 255) / 256, 256>>>(ginW1, gcnW, ginW2, whpW, preW, embW);

    // CSR build
    hist_k<<<gridE, TB>>>(ei);
    scan1_k<<<NB1, 1024>>>();
    scan2_k<<<1, 64>>>();
    scan3_k<<<gridN, TB>>>();
    fill_k<<<gridE, TB>>>(ei);

    // pre: x(fp32) -> xc[:, :64];  emb: s(fp32) -> xc[:, 64:]
    hgemm_k<128, 64, 0, 1, 1><<<gridM, 256, SM128>>>(x_in, 128, w16 + W_PRE, preb, NN,
                                                     xc16, 128, nullptr, 0);
    hgemm_k<16, 64, 0, 1, 1><<<gridM, 256, SM16>>>(s_in, 16, w16 + W_EMB, embb, NN,
                                                   xc16 + 64, 128, nullptr, 0);

    for (int i = 0; i < LL; i++) {
        // dual: y = xc @ ginW1, hs = s @ gcnW in ONE pass over xc
        hgemm_k<128, 128, 0, 1, 0><<<gridM, 256, SMDUAL>>>(xc16, 128, w16 + W_DUAL + i * 16384,
                                                           nullptr, NN, p_y16, 64, p_hs16, 64);
        agg_fused_k<<<gridW, TB>>>(ginb1 + i * 64, gcnb + i * 64);
        hgemm_k<64, 64, 1, 1, 0><<<gridM, 256, SM64>>>(p_z16, 64, w16 + W_GIN2 + i * 4096,
                                                       ginb2 + i * 64, NN, xc16, 128, nullptr, 0);
    }

    hgemm_k<128, 64, 0, 0, 0><<<gridM, 256, SM128>>>(xc16, 128, w16 + W_WHP, whpb, NN,
                                                     p_x2, 64, nullptr, 0);
    poolhead_k<<<GG, 64>>>(batch, postW, postb, roW, rob, out);
}